// round 1
// baseline (speedup 1.0000x reference)
#include <cuda_runtime.h>

__device__ __forceinline__ float fast_tanh(float x) {
    float y;
    asm("tanh.approx.f32 %0, %1;" : "=f"(y) : "f"(x));
    return y;
}

// Gate row order in the 4H=20 dimension: i=[0,5), f=[5,10), g=[10,15), o=[15,20)
// For i/f/o we compute sigmoid(z) = 0.5*tanh(z/2)+0.5 and fold the 1/2 into the
// weights/bias at load time, so each sigmoid costs 1 MUFU.TANH + 1 FFMA.
__global__ __launch_bounds__(128) void lstm_kernel(
    const float* __restrict__ x,      // (32768, 600)
    const float* __restrict__ w_ih,   // (20, 1)
    const float* __restrict__ w_hh,   // (20, 5)
    const float* __restrict__ b_ih,   // (20,)
    const float* __restrict__ b_hh,   // (20,)
    const float* __restrict__ fc_w,   // (15, 5)
    const float* __restrict__ fc_b,   // (15,)
    const float* __restrict__ out_w,  // (1, 15)
    const float* __restrict__ out_b,  // (1,)
    float* __restrict__ out)          // (32768,)
{
    __shared__ float s_wih[20];
    __shared__ float s_whh[100];
    __shared__ float s_b[20];
    __shared__ float s_fcw[75];
    __shared__ float s_fcb[15];
    __shared__ float s_outw[15];
    __shared__ float s_outb;

    const int tid = threadIdx.x;
    if (tid < 20) {
        // scale i, f, o rows by 0.5 (sigmoid-via-tanh); g row (10..14) unscaled
        const float sc = (tid < 10 || tid >= 15) ? 0.5f : 1.0f;
        s_wih[tid] = w_ih[tid] * sc;
        s_b[tid]   = (b_ih[tid] + b_hh[tid]) * sc;
        #pragma unroll
        for (int j = 0; j < 5; j++) s_whh[tid * 5 + j] = w_hh[tid * 5 + j] * sc;
    }
    if (tid < 75) s_fcw[tid] = fc_w[tid];
    if (tid < 15) { s_fcb[tid] = fc_b[tid]; s_outw[tid] = out_w[tid]; }
    if (tid == 0) s_outb = out_b[0];
    __syncthreads();

    const int seq = blockIdx.x * 128 + tid;
    const float* xr = x + (long)seq * 600;

    float h[5] = {0.f, 0.f, 0.f, 0.f, 0.f};
    float c[5] = {0.f, 0.f, 0.f, 0.f, 0.f};

    #pragma unroll 1
    for (int t0 = 0; t0 < 600; t0 += 4) {
        const float4 xv = *reinterpret_cast<const float4*>(xr + t0);
        float xs[4] = {xv.x, xv.y, xv.z, xv.w};
        #pragma unroll
        for (int u = 0; u < 4; u++) {
            const float xt = xs[u];
            float gi[5], gf[5], gg[5], go[5];
            #pragma unroll
            for (int j = 0; j < 5; j++) {
                float a0 = fmaf(xt, s_wih[j],      s_b[j]);
                float a1 = fmaf(xt, s_wih[5 + j],  s_b[5 + j]);
                float a2 = fmaf(xt, s_wih[10 + j], s_b[10 + j]);
                float a3 = fmaf(xt, s_wih[15 + j], s_b[15 + j]);
                #pragma unroll
                for (int k = 0; k < 5; k++) {
                    a0 = fmaf(h[k], s_whh[j * 5 + k],        a0);
                    a1 = fmaf(h[k], s_whh[(5 + j) * 5 + k],  a1);
                    a2 = fmaf(h[k], s_whh[(10 + j) * 5 + k], a2);
                    a3 = fmaf(h[k], s_whh[(15 + j) * 5 + k], a3);
                }
                gi[j] = a0; gf[j] = a1; gg[j] = a2; go[j] = a3;
            }
            #pragma unroll
            for (int j = 0; j < 5; j++) {
                const float iv = fmaf(fast_tanh(gi[j]), 0.5f, 0.5f);
                const float fv = fmaf(fast_tanh(gf[j]), 0.5f, 0.5f);
                const float gv = fast_tanh(gg[j]);
                const float ov = fmaf(fast_tanh(go[j]), 0.5f, 0.5f);
                c[j] = fmaf(fv, c[j], iv * gv);
                h[j] = ov * fast_tanh(c[j]);
            }
        }
    }

    // Epilogue: hid = h @ fc_w^T + fc_b ; out = hid @ out_w^T + out_b ; sigmoid
    float acc = s_outb;
    #pragma unroll
    for (int k = 0; k < 15; k++) {
        float hv = s_fcb[k];
        #pragma unroll
        for (int j = 0; j < 5; j++) hv = fmaf(h[j], s_fcw[k * 5 + j], hv);
        acc = fmaf(hv, s_outw[k], acc);
    }
    out[seq] = 1.0f / (1.0f + __expf(-acc));
}

extern "C" void kernel_launch(void* const* d_in, const int* in_sizes, int n_in,
                              void* d_out, int out_size) {
    const float* x    = (const float*)d_in[0];
    const float* w_ih = (const float*)d_in[1];
    const float* w_hh = (const float*)d_in[2];
    const float* b_ih = (const float*)d_in[3];
    const float* b_hh = (const float*)d_in[4];
    const float* fc_w = (const float*)d_in[5];
    const float* fc_b = (const float*)d_in[6];
    const float* out_w = (const float*)d_in[7];
    const float* out_b = (const float*)d_in[8];
    float* out = (float*)d_out;

    // 32768 sequences, 1 per thread: 256 blocks x 128 threads
    lstm_kernel<<<256, 128>>>(x, w_ih, w_hh, b_ih, b_hh, fc_w, fc_b,
                              out_w, out_b, out);
}